// round 2
// baseline (speedup 1.0000x reference)
#include <cuda_runtime.h>
#include <math.h>

#define NTOK   98304
#define CDIM   64
#define KCODES 1024

// ---- scratch (no allocations allowed; __device__ globals per harness rules) ----
__device__ float g_buf0[(size_t)NTOK * 512];
__device__ float g_buf1[(size_t)NTOK * 512];
__device__ float g_lat [(size_t)NTOK * CDIM];
__device__ float g_dw  [CDIM * KCODES];
__device__ int   g_counts[KCODES];
__device__ float g_enorm [KCODES];
__device__ float g_loss;

__device__ __forceinline__ float gelu_tanh(float x) {
    // jax.nn.gelu default (tanh approximation)
    float x3 = x * x * x;
    return 0.5f * x * (1.0f + tanhf(0.7978845608028654f * (x + 0.044715f * x3)));
}

// Zero accumulators + precompute code norms: sum_c emb[c][j]^2
__global__ void init_kernel(const float* __restrict__ emb) {
    int t = threadIdx.x;  // 1024 threads
    for (int i = t; i < CDIM * KCODES; i += 1024) g_dw[i] = 0.f;
    g_counts[t] = 0;
    if (t == 0) g_loss = 0.f;
    float s = 0.f;
    #pragma unroll
    for (int c = 0; c < CDIM; c++) {
        float v = emb[c * KCODES + t];
        s = fmaf(v, v, s);
    }
    g_enorm[t] = s;
}

// ---- fp32 tiled GEMM + bias + gelu: C[N,M] = gelu(A[N,K] @ W[K,M] + b) ----
// TM=128 rows, TN columns (128 or 64), TK=16. 256 threads, 16x16 layout,
// micro-tile 8 x (TN/16).
template <int TN>
__global__ __launch_bounds__(256) void gemm_bias_gelu(
    const float* __restrict__ A, const float* __restrict__ W,
    const float* __restrict__ bias, float* __restrict__ C,
    int N, int K, int M)
{
    constexpr int TM = 128, TK = 16;
    constexpr int NR = TN / 16;  // cols per thread
    __shared__ float As[TK][TM];
    __shared__ float Bs[TK][TN];

    const int tid = threadIdx.x;
    const int bm = blockIdx.y * TM;
    const int bn = blockIdx.x * TN;
    const int mt = (tid & 15) * 8;
    const int nt = (tid >> 4) * NR;

    float acc[8][NR];
    #pragma unroll
    for (int i = 0; i < 8; i++)
        #pragma unroll
        for (int j = 0; j < NR; j++) acc[i][j] = 0.f;

    for (int k0 = 0; k0 < K; k0 += TK) {
        // A tile: 128x16 = 512 float4, 2 per thread. Stored transposed As[k][m].
        #pragma unroll
        for (int i = 0; i < 2; i++) {
            int e = tid + i * 256;          // 0..511
            int row = e >> 2;               // 0..127
            int q = (e & 3) << 2;           // 0,4,8,12
            float4 v = *reinterpret_cast<const float4*>(
                A + (size_t)(bm + row) * K + k0 + q);
            As[q + 0][row] = v.x; As[q + 1][row] = v.y;
            As[q + 2][row] = v.z; As[q + 3][row] = v.w;
        }
        // B tile: 16 x TN
        #pragma unroll
        for (int i = 0; i < TN / 64; i++) {
            int e = tid + i * 256;
            int kk = e / (TN / 4);
            int c4 = (e % (TN / 4)) * 4;
            *reinterpret_cast<float4*>(&Bs[kk][c4]) =
                *reinterpret_cast<const float4*>(W + (size_t)(k0 + kk) * M + bn + c4);
        }
        __syncthreads();

        #pragma unroll
        for (int kk = 0; kk < TK; kk++) {
            float a[8], b[NR];
            #pragma unroll
            for (int i = 0; i < 8; i++) a[i] = As[kk][mt + i];
            #pragma unroll
            for (int j = 0; j < NR; j++) b[j] = Bs[kk][nt + j];
            #pragma unroll
            for (int i = 0; i < 8; i++)
                #pragma unroll
                for (int j = 0; j < NR; j++)
                    acc[i][j] = fmaf(a[i], b[j], acc[i][j]);
        }
        __syncthreads();
    }

    #pragma unroll
    for (int i = 0; i < 8; i++) {
        float* crow = C + (size_t)(bm + mt + i) * M + bn + nt;
        #pragma unroll
        for (int j = 0; j < NR; j++) {
            float v = acc[i][j] + bias[bn + nt + j];
            crow[j] = gelu_tanh(v);
        }
    }
}

// ---- VQ: per-token argmin over 1024 codes; writes quantized + idx; scatters stats ----
// 256 tokens per block (one per thread); codes staged in smem 64 at a time.
__global__ __launch_bounds__(256) void vq_kernel(
    const float* __restrict__ latent, const float* __restrict__ emb,
    float* __restrict__ out_q, float* __restrict__ out_idx)
{
    __shared__ float se[64][68];   // [code][dim], padded for alignment/banks
    __shared__ float sn[64];
    __shared__ float wsum[8];

    const int tok = blockIdx.x * 256 + threadIdx.x;
    float f[64];
    #pragma unroll
    for (int c = 0; c < 64; c += 4) {
        float4 v = *reinterpret_cast<const float4*>(latent + (size_t)tok * 64 + c);
        f[c] = v.x; f[c + 1] = v.y; f[c + 2] = v.z; f[c + 3] = v.w;
    }

    float best = -3.4e38f;
    int bestj = 0;
    for (int ch = 0; ch < KCODES; ch += 64) {
        #pragma unroll
        for (int r = 0; r < 16; r++) {
            int e = threadIdx.x + r * 256;
            int c = e >> 6, j = e & 63;
            se[j][c] = emb[c * KCODES + ch + j];
        }
        if (threadIdx.x < 64) sn[threadIdx.x] = g_enorm[ch + threadIdx.x];
        __syncthreads();

        #pragma unroll 4
        for (int j = 0; j < 64; j++) {
            const float4* row = reinterpret_cast<const float4*>(&se[j][0]);
            float dot = 0.f;
            #pragma unroll
            for (int cc = 0; cc < 16; cc++) {
                float4 v = row[cc];
                dot = fmaf(f[4 * cc + 0], v.x, dot);
                dot = fmaf(f[4 * cc + 1], v.y, dot);
                dot = fmaf(f[4 * cc + 2], v.z, dot);
                dot = fmaf(f[4 * cc + 3], v.w, dot);
            }
            float score = 2.f * dot - sn[j];  // argmax == argmin distance
            if (score > best) { best = score; bestj = ch + j; }  // first-max on ties
        }
        __syncthreads();
    }

    out_idx[tok] = (float)bestj;

    float lsum = 0.f;
    #pragma unroll
    for (int c = 0; c < 64; c++) {
        float q = __ldg(&emb[c * KCODES + bestj]);
        out_q[(size_t)tok * 64 + c] = q;
        float d = q - f[c];
        lsum = fmaf(d, d, lsum);
        atomicAdd(&g_dw[c * KCODES + bestj], f[c]);
    }
    atomicAdd(&g_counts[bestj], 1);

    #pragma unroll
    for (int o = 16; o > 0; o >>= 1)
        lsum += __shfl_down_sync(0xffffffffu, lsum, o);
    int lane = threadIdx.x & 31, w = threadIdx.x >> 5;
    if (lane == 0) wsum[w] = lsum;
    __syncthreads();
    if (threadIdx.x == 0) {
        float s = 0.f;
        #pragma unroll
        for (int i = 0; i < 8; i++) s += wsum[i];
        atomicAdd(&g_loss, s);
    }
}

// ---- EMA finalize: loss, perplexity, new_embeddings ----
__global__ void finalize_kernel(
    const float* __restrict__ ema_cluster, const float* __restrict__ ema_dw,
    float* __restrict__ out_loss, float* __restrict__ out_perp,
    float* __restrict__ out_emb)
{
    __shared__ float red[1024];
    int j = threadIdx.x;
    const float debias = (float)(1.0 - pow(0.99, 1001.0));

    float cnt = (float)g_counts[j];
    float cs = (ema_cluster[j] * 0.99f + cnt * 0.01f) / debias;

    red[j] = cs;
    __syncthreads();
    for (int s = 512; s > 0; s >>= 1) {
        if (j < s) red[j] += red[j + s];
        __syncthreads();
    }
    float n = red[0];
    __syncthreads();

    float stable = (cs + 1e-5f) / (n + 1024.f * 1e-5f) * n;
    for (int c = 0; c < 64; c++) {
        int idx = c * 1024 + j;
        float upd = (ema_dw[idx] * 0.99f + g_dw[idx] * 0.01f) / debias;
        out_emb[idx] = upd / stable;
    }

    float ap = cnt / (float)NTOK;
    red[j] = ap * logf(ap + 1e-10f);
    __syncthreads();
    for (int s = 512; s > 0; s >>= 1) {
        if (j < s) red[j] += red[j + s];
        __syncthreads();
    }
    if (j == 0) {
        out_perp[0] = expf(-red[0]);
        out_loss[0] = 0.25f * (g_loss / (float)((size_t)NTOK * CDIM));
    }
}

extern "C" void kernel_launch(void* const* d_in, const int* in_sizes, int n_in,
                              void* d_out, int out_size)
{
    const float* states      = (const float*)d_in[0];
    const float* w_se        = (const float*)d_in[1];
    const float* b_se        = (const float*)d_in[2];
    const float* w0          = (const float*)d_in[3];
    const float* b0          = (const float*)d_in[4];
    const float* w1          = (const float*)d_in[5];
    const float* b1          = (const float*)d_in[6];
    const float* w2          = (const float*)d_in[7];
    const float* b2          = (const float*)d_in[8];
    const float* emb         = (const float*)d_in[9];
    const float* ema_cluster = (const float*)d_in[10];
    const float* ema_dw      = (const float*)d_in[11];
    float* out = (float*)d_out;

    float *buf0, *buf1, *lat;
    cudaGetSymbolAddress((void**)&buf0, g_buf0);
    cudaGetSymbolAddress((void**)&buf1, g_buf1);
    cudaGetSymbolAddress((void**)&lat,  g_lat);

    // Output layout: quantized [0,6291456), loss, perplexity,
    // enc_idx [6291458, +98304), new_embeddings [6389762, +65536)
    float* out_q    = out;
    float* out_loss = out + 6291456;
    float* out_perp = out + 6291457;
    float* out_idx  = out + 6291458;
    float* out_emb  = out + 6389762;

    init_kernel<<<1, 1024>>>(emb);

    gemm_bias_gelu<128><<<dim3(4, NTOK / 128), 256>>>(states, w_se, b_se, buf0, NTOK, 256, 512);
    gemm_bias_gelu<128><<<dim3(4, NTOK / 128), 256>>>(buf0,   w0,   b0,   buf1, NTOK, 512, 512);
    gemm_bias_gelu<128><<<dim3(4, NTOK / 128), 256>>>(buf1,   w1,   b1,   buf0, NTOK, 512, 512);
    gemm_bias_gelu<64> <<<dim3(1, NTOK / 128), 256>>>(buf0,   w2,   b2,   lat,  NTOK, 512, 64);

    vq_kernel<<<NTOK / 256, 256>>>(lat, emb, out_q, out_idx);

    finalize_kernel<<<1, 1024>>>(ema_cluster, ema_dw, out_loss, out_perp, out_emb);
}

// round 3
// speedup vs baseline: 1.0217x; 1.0217x over previous
#include <cuda_runtime.h>
#include <math.h>

#define NTOK   98304
#define CDIM   64
#define KCODES 1024

// ---- scratch (no allocations allowed; __device__ globals per harness rules) ----
__device__ float g_buf0[(size_t)NTOK * 512];
__device__ float g_buf1[(size_t)NTOK * 512];
__device__ float g_lat [(size_t)NTOK * CDIM];
__device__ float g_dw  [CDIM * KCODES];
__device__ int   g_counts[KCODES];
__device__ float g_enorm [KCODES];
__device__ float g_loss;

__device__ __forceinline__ float gelu_tanh(float x) {
    float x3 = x * x * x;
    return 0.5f * x * (1.0f + tanhf(0.7978845608028654f * (x + 0.044715f * x3)));
}

// Zero accumulators + precompute code norms: sum_c emb[c][j]^2
__global__ void init_kernel(const float* __restrict__ emb) {
    int t = threadIdx.x;  // 1024 threads
    for (int i = t; i < CDIM * KCODES; i += 1024) g_dw[i] = 0.f;
    g_counts[t] = 0;
    if (t == 0) g_loss = 0.f;
    float s = 0.f;
    #pragma unroll
    for (int c = 0; c < CDIM; c++) {
        float v = emb[c * KCODES + t];
        s = fmaf(v, v, s);
    }
    g_enorm[t] = s;
}

// ---- fp32 software-pipelined GEMM + bias + gelu ----
// C[N,M] = gelu(A[N,K] @ W[K,M] + b). TM=128, TN in {128,64}, TK=8.
// 256 threads, 16x16 layout, micro-tile 8 x (TN/16). Double-buffered smem:
// prefetch next k-tile into registers during compute, 1 barrier per tile.
template <int TN>
__global__ __launch_bounds__(256, 2) void gemm_bias_gelu(
    const float* __restrict__ A, const float* __restrict__ W,
    const float* __restrict__ bias, float* __restrict__ C,
    int N, int K, int M)
{
    constexpr int TM = 128, TK = 8;
    constexpr int NR = TN / 16;            // cols per thread
    constexpr int BLOAD = (TK * TN) / 4;   // float4s in a B tile
    __shared__ float As[2][TK][TM];
    __shared__ float Bs[2][TK][TN];

    const int tid = threadIdx.x;
    const int bm = blockIdx.y * TM;
    const int bn = blockIdx.x * TN;
    const int mt = (tid & 15) * 8;
    const int nt = (tid >> 4) * NR;

    // A tile: 128 rows x 8 floats = 256 float4, one per thread.
    const int arow = tid >> 1;
    const int acol = (tid & 1) * 4;
    // B tile: 8 x TN floats = BLOAD float4.
    const int brow = (tid < BLOAD) ? tid / (TN / 4) : 0;
    const int bcol = (tid < BLOAD) ? (tid % (TN / 4)) * 4 : 0;

    const float* Aptr = A + (size_t)(bm + arow) * K + acol;
    const float* Wptr = W + (size_t)brow * M + bn + bcol;

    float acc[8][NR];
    #pragma unroll
    for (int i = 0; i < 8; i++)
        #pragma unroll
        for (int j = 0; j < NR; j++) acc[i][j] = 0.f;

    // Prologue: tile 0 -> buffer 0
    float4 ar = *reinterpret_cast<const float4*>(Aptr);
    float4 br;
    if (tid < BLOAD) br = *reinterpret_cast<const float4*>(Wptr);
    As[0][acol + 0][arow] = ar.x; As[0][acol + 1][arow] = ar.y;
    As[0][acol + 2][arow] = ar.z; As[0][acol + 3][arow] = ar.w;
    if (tid < BLOAD) *reinterpret_cast<float4*>(&Bs[0][brow][bcol]) = br;
    __syncthreads();

    int buf = 0;
    for (int k0 = 0; k0 < K; k0 += TK) {
        const bool more = (k0 + TK) < K;
        // Issue next tile's global loads (latency hides under compute)
        if (more) {
            ar = *reinterpret_cast<const float4*>(Aptr + k0 + TK);
            if (tid < BLOAD)
                br = *reinterpret_cast<const float4*>(Wptr + (size_t)(k0 + TK) * M);
        }

        // Compute current tile
        #pragma unroll
        for (int kk = 0; kk < TK; kk++) {
            float a[8], b[NR];
            #pragma unroll
            for (int i = 0; i < 8; i++) a[i] = As[buf][kk][mt + i];
            #pragma unroll
            for (int j = 0; j < NR; j++) b[j] = Bs[buf][kk][nt + j];
            #pragma unroll
            for (int i = 0; i < 8; i++)
                #pragma unroll
                for (int j = 0; j < NR; j++)
                    acc[i][j] = fmaf(a[i], b[j], acc[i][j]);
        }

        // Stage next tile into the alternate buffer (safe: that buffer was
        // last read before the previous barrier)
        if (more) {
            int nb = buf ^ 1;
            As[nb][acol + 0][arow] = ar.x; As[nb][acol + 1][arow] = ar.y;
            As[nb][acol + 2][arow] = ar.z; As[nb][acol + 3][arow] = ar.w;
            if (tid < BLOAD) *reinterpret_cast<float4*>(&Bs[nb][brow][bcol]) = br;
        }
        __syncthreads();
        buf ^= 1;
    }

    #pragma unroll
    for (int i = 0; i < 8; i++) {
        float* crow = C + (size_t)(bm + mt + i) * M + bn + nt;
        #pragma unroll
        for (int j = 0; j < NR; j++) {
            float v = acc[i][j] + bias[bn + nt + j];
            crow[j] = gelu_tanh(v);
        }
    }
}

// ---- VQ: per-token argmin over 1024 codes; writes quantized + idx; scatters stats ----
__global__ __launch_bounds__(256) void vq_kernel(
    const float* __restrict__ latent, const float* __restrict__ emb,
    float* __restrict__ out_q, float* __restrict__ out_idx)
{
    __shared__ float se[64][68];
    __shared__ float sn[64];
    __shared__ float wsum[8];

    const int tok = blockIdx.x * 256 + threadIdx.x;
    float f[64];
    #pragma unroll
    for (int c = 0; c < 64; c += 4) {
        float4 v = *reinterpret_cast<const float4*>(latent + (size_t)tok * 64 + c);
        f[c] = v.x; f[c + 1] = v.y; f[c + 2] = v.z; f[c + 3] = v.w;
    }

    float best = -3.4e38f;
    int bestj = 0;
    for (int ch = 0; ch < KCODES; ch += 64) {
        #pragma unroll
        for (int r = 0; r < 16; r++) {
            int e = threadIdx.x + r * 256;
            int c = e >> 6, j = e & 63;
            se[j][c] = emb[c * KCODES + ch + j];
        }
        if (threadIdx.x < 64) sn[threadIdx.x] = g_enorm[ch + threadIdx.x];
        __syncthreads();

        #pragma unroll 4
        for (int j = 0; j < 64; j++) {
            const float4* row = reinterpret_cast<const float4*>(&se[j][0]);
            float dot = 0.f;
            #pragma unroll
            for (int cc = 0; cc < 16; cc++) {
                float4 v = row[cc];
                dot = fmaf(f[4 * cc + 0], v.x, dot);
                dot = fmaf(f[4 * cc + 1], v.y, dot);
                dot = fmaf(f[4 * cc + 2], v.z, dot);
                dot = fmaf(f[4 * cc + 3], v.w, dot);
            }
            float score = 2.f * dot - sn[j];
            if (score > best) { best = score; bestj = ch + j; }
        }
        __syncthreads();
    }

    out_idx[tok] = (float)bestj;

    float lsum = 0.f;
    #pragma unroll
    for (int c = 0; c < 64; c++) {
        float q = __ldg(&emb[c * KCODES + bestj]);
        out_q[(size_t)tok * 64 + c] = q;
        float d = q - f[c];
        lsum = fmaf(d, d, lsum);
        atomicAdd(&g_dw[c * KCODES + bestj], f[c]);
    }
    atomicAdd(&g_counts[bestj], 1);

    #pragma unroll
    for (int o = 16; o > 0; o >>= 1)
        lsum += __shfl_down_sync(0xffffffffu, lsum, o);
    int lane = threadIdx.x & 31, w = threadIdx.x >> 5;
    if (lane == 0) wsum[w] = lsum;
    __syncthreads();
    if (threadIdx.x == 0) {
        float s = 0.f;
        #pragma unroll
        for (int i = 0; i < 8; i++) s += wsum[i];
        atomicAdd(&g_loss, s);
    }
}

// ---- EMA finalize: loss, perplexity, new_embeddings ----
__global__ void finalize_kernel(
    const float* __restrict__ ema_cluster, const float* __restrict__ ema_dw,
    float* __restrict__ out_loss, float* __restrict__ out_perp,
    float* __restrict__ out_emb)
{
    __shared__ float red[1024];
    int j = threadIdx.x;
    const float debias = (float)(1.0 - pow(0.99, 1001.0));

    float cnt = (float)g_counts[j];
    float cs = (ema_cluster[j] * 0.99f + cnt * 0.01f) / debias;

    red[j] = cs;
    __syncthreads();
    for (int s = 512; s > 0; s >>= 1) {
        if (j < s) red[j] += red[j + s];
        __syncthreads();
    }
    float n = red[0];
    __syncthreads();

    float stable = (cs + 1e-5f) / (n + 1024.f * 1e-5f) * n;
    for (int c = 0; c < 64; c++) {
        int idx = c * 1024 + j;
        float upd = (ema_dw[idx] * 0.99f + g_dw[idx] * 0.01f) / debias;
        out_emb[idx] = upd / stable;
    }

    float ap = cnt / (float)NTOK;
    red[j] = ap * logf(ap + 1e-10f);
    __syncthreads();
    for (int s = 512; s > 0; s >>= 1) {
        if (j < s) red[j] += red[j + s];
        __syncthreads();
    }
    if (j == 0) {
        out_perp[0] = expf(-red[0]);
        out_loss[0] = 0.25f * (g_loss / (float)((size_t)NTOK * CDIM));
    }
}

extern "C" void kernel_launch(void* const* d_in, const int* in_sizes, int n_in,
                              void* d_out, int out_size)
{
    const float* states      = (const float*)d_in[0];
    const float* w_se        = (const float*)d_in[1];
    const float* b_se        = (const float*)d_in[2];
    const float* w0          = (const float*)d_in[3];
    const float* b0          = (const float*)d_in[4];
    const float* w1          = (const float*)d_in[5];
    const float* b1          = (const float*)d_in[6];
    const float* w2          = (const float*)d_in[7];
    const float* b2          = (const float*)d_in[8];
    const float* emb         = (const float*)d_in[9];
    const float* ema_cluster = (const float*)d_in[10];
    const float* ema_dw      = (const float*)d_in[11];
    float* out = (float*)d_out;

    float *buf0, *buf1, *lat;
    cudaGetSymbolAddress((void**)&buf0, g_buf0);
    cudaGetSymbolAddress((void**)&buf1, g_buf1);
    cudaGetSymbolAddress((void**)&lat,  g_lat);

    float* out_q    = out;
    float* out_loss = out + 6291456;
    float* out_perp = out + 6291457;
    float* out_idx  = out + 6291458;
    float* out_emb  = out + 6389762;

    init_kernel<<<1, 1024>>>(emb);

    gemm_bias_gelu<128><<<dim3(4, NTOK / 128), 256>>>(states, w_se, b_se, buf0, NTOK, 256, 512);
    gemm_bias_gelu<128><<<dim3(4, NTOK / 128), 256>>>(buf0,   w0,   b0,   buf1, NTOK, 512, 512);
    gemm_bias_gelu<128><<<dim3(4, NTOK / 128), 256>>>(buf1,   w1,   b1,   buf0, NTOK, 512, 512);
    gemm_bias_gelu<64> <<<dim3(1, NTOK / 128), 256>>>(buf0,   w2,   b2,   lat,  NTOK, 512, 64);

    vq_kernel<<<NTOK / 256, 256>>>(lat, emb, out_q, out_idx);

    finalize_kernel<<<1, 1024>>>(ema_cluster, ema_dw, out_loss, out_perp, out_emb);
}

// round 10
// speedup vs baseline: 1.0897x; 1.0666x over previous
#include <cuda_runtime.h>
#include <math.h>

#define NTOK   98304
#define CDIM   64
#define KCODES 1024

typedef unsigned long long ull;

// ---- scratch (no allocations allowed; __device__ globals per harness rules) ----
__device__ float g_buf0[(size_t)NTOK * 512];
__device__ float g_buf1[(size_t)NTOK * 512];
__device__ float g_lat [(size_t)NTOK * CDIM];
__device__ float g_dw  [CDIM * KCODES];
__device__ int   g_counts[KCODES];
__device__ float g_enorm [KCODES];
__device__ float g_loss;

__device__ __forceinline__ float gelu_tanh(float x) {
    float x3 = x * x * x;
    return 0.5f * x * (1.0f + tanhf(0.7978845608028654f * (x + 0.044715f * x3)));
}

// Packed dual-fp32 FMA (Blackwell f32x2 pipe; ptxas never emits this from C++)
__device__ __forceinline__ ull fma2(ull a, ull b, ull c) {
    ull d;
    asm("fma.rn.f32x2 %0, %1, %2, %3;" : "=l"(d) : "l"(a), "l"(b), "l"(c));
    return d;
}
__device__ __forceinline__ ull dup2(float x) {
    ull d;
    asm("mov.b64 %0, {%1, %1};" : "=l"(d) : "f"(x));
    return d;
}
__device__ __forceinline__ ull pack2(float lo, float hi) {
    ull d;
    asm("mov.b64 %0, {%1, %2};" : "=l"(d) : "f"(lo), "f"(hi));
    return d;
}
__device__ __forceinline__ void unpack2(ull d, float& lo, float& hi) {
    asm("mov.b64 {%0, %1}, %2;" : "=f"(lo), "=f"(hi) : "l"(d));
}

// Zero accumulators + precompute code norms: sum_c emb[c][j]^2
__global__ void init_kernel(const float* __restrict__ emb) {
    int t = threadIdx.x;  // 1024 threads
    for (int i = t; i < CDIM * KCODES; i += 1024) g_dw[i] = 0.f;
    g_counts[t] = 0;
    if (t == 0) g_loss = 0.f;
    float s = 0.f;
    #pragma unroll
    for (int c = 0; c < CDIM; c++) {
        float v = emb[c * KCODES + t];
        s = fmaf(v, v, s);
    }
    g_enorm[t] = s;
}

// ---- fp32 GEMM + bias + gelu, f32x2-packed inner product ----
// C[N,M] = gelu(A[N,K] @ W[K,M] + b). TM=128, TN in {128,64}, TK=8.
// 256 threads, micro-tile 8 x NR per thread; acc packed in pairs over N.
template <int TN>
__global__ __launch_bounds__(256, 2) void gemm_bias_gelu(
    const float* __restrict__ A, const float* __restrict__ W,
    const float* __restrict__ bias, float* __restrict__ C,
    int N, int K, int M)
{
    constexpr int TM = 128, TK = 8;
    constexpr int NR = TN / 16;            // cols per thread (8 or 4)
    constexpr int NP = NR / 2;             // packed col-pairs per thread
    constexpr int BLOAD = (TK * TN) / 4;   // float4s in a B tile
    __shared__ __align__(16) float As[2][TK][TM];
    __shared__ __align__(16) float Bs[2][TK][TN];

    const int tid = threadIdx.x;
    const int bm = blockIdx.y * TM;
    const int bn = blockIdx.x * TN;
    const int mt = (tid & 15) * 8;
    const int nt = (tid >> 4) * NR;

    // A tile: 128 rows x 8 floats = 256 float4, one per thread.
    const int arow = tid >> 1;
    const int acol = (tid & 1) * 4;
    // B tile: 8 x TN floats = BLOAD float4.
    const int brow = (tid < BLOAD) ? tid / (TN / 4) : 0;
    const int bcol = (tid < BLOAD) ? (tid % (TN / 4)) * 4 : 0;

    const float* Aptr = A + (size_t)(bm + arow) * K + acol;
    const float* Wptr = W + (size_t)brow * M + bn + bcol;

    ull acc2[8][NP];
    #pragma unroll
    for (int i = 0; i < 8; i++)
        #pragma unroll
        for (int j = 0; j < NP; j++) acc2[i][j] = 0ull;  // {+0.f, +0.f}

    // Prologue: tile 0 -> buffer 0
    float4 ar = *reinterpret_cast<const float4*>(Aptr);
    float4 br;
    if (tid < BLOAD) br = *reinterpret_cast<const float4*>(Wptr);
    As[0][acol + 0][arow] = ar.x; As[0][acol + 1][arow] = ar.y;
    As[0][acol + 2][arow] = ar.z; As[0][acol + 3][arow] = ar.w;
    if (tid < BLOAD) *reinterpret_cast<float4*>(&Bs[0][brow][bcol]) = br;
    __syncthreads();

    int buf = 0;
    for (int k0 = 0; k0 < K; k0 += TK) {
        const bool more = (k0 + TK) < K;
        if (more) {
            ar = *reinterpret_cast<const float4*>(Aptr + k0 + TK);
            if (tid < BLOAD)
                br = *reinterpret_cast<const float4*>(Wptr + (size_t)(k0 + TK) * M);
        }

        #pragma unroll
        for (int kk = 0; kk < TK; kk++) {
            // A fragment: 8 scalars (2x LDS.128)
            float4 a0 = *reinterpret_cast<const float4*>(&As[buf][kk][mt]);
            float4 a1 = *reinterpret_cast<const float4*>(&As[buf][kk][mt + 4]);
            float a[8] = {a0.x, a0.y, a0.z, a0.w, a1.x, a1.y, a1.z, a1.w};
            // B fragment: NP packed pairs. One ulonglong2 = 4 consecutive
            // floats = pairs {2p, 2p+1}, stepping 4 floats per load.
            ull b2[NP];
            #pragma unroll
            for (int p = 0; p < NP / 2; p++) {
                ulonglong2 t = *reinterpret_cast<const ulonglong2*>(&Bs[buf][kk][nt + 4 * p]);
                b2[2 * p] = t.x; b2[2 * p + 1] = t.y;
            }
            #pragma unroll
            for (int i = 0; i < 8; i++) {
                ull ad = dup2(a[i]);
                #pragma unroll
                for (int j = 0; j < NP; j++)
                    acc2[i][j] = fma2(ad, b2[j], acc2[i][j]);
            }
        }

        if (more) {
            int nb = buf ^ 1;
            As[nb][acol + 0][arow] = ar.x; As[nb][acol + 1][arow] = ar.y;
            As[nb][acol + 2][arow] = ar.z; As[nb][acol + 3][arow] = ar.w;
            if (tid < BLOAD) *reinterpret_cast<float4*>(&Bs[nb][brow][bcol]) = br;
        }
        __syncthreads();
        buf ^= 1;
    }

    // Epilogue: unpack pairs, bias + gelu, vectorized store
    float bv[NR];
    #pragma unroll
    for (int j = 0; j < NR; j++) bv[j] = bias[bn + nt + j];
    #pragma unroll
    for (int i = 0; i < 8; i++) {
        float o[NR];
        #pragma unroll
        for (int j = 0; j < NP; j++) {
            float lo, hi;
            unpack2(acc2[i][j], lo, hi);
            o[2 * j]     = gelu_tanh(lo + bv[2 * j]);
            o[2 * j + 1] = gelu_tanh(hi + bv[2 * j + 1]);
        }
        float* crow = C + (size_t)(bm + mt + i) * M + bn + nt;
        #pragma unroll
        for (int j = 0; j < NR / 4; j++)
            *reinterpret_cast<float4*>(crow + 4 * j) =
                make_float4(o[4 * j], o[4 * j + 1], o[4 * j + 2], o[4 * j + 3]);
    }
}

// ---- VQ: per-token argmin over 1024 codes (f32x2 dot), scatter stats ----
__global__ __launch_bounds__(256) void vq_kernel(
    const float* __restrict__ latent, const float* __restrict__ emb,
    float* __restrict__ out_q, float* __restrict__ out_idx)
{
    __shared__ __align__(16) float se[64][68];
    __shared__ float sn[64];
    __shared__ float wsum[8];

    const int tok = blockIdx.x * 256 + threadIdx.x;
    ull f2[32];
    #pragma unroll
    for (int c = 0; c < 64; c += 4) {
        float4 v = *reinterpret_cast<const float4*>(latent + (size_t)tok * 64 + c);
        f2[c / 2]     = pack2(v.x, v.y);
        f2[c / 2 + 1] = pack2(v.z, v.w);
    }

    float best = -3.4e38f;
    int bestj = 0;
    for (int ch = 0; ch < KCODES; ch += 64) {
        #pragma unroll
        for (int r = 0; r < 16; r++) {
            int e = threadIdx.x + r * 256;
            int c = e >> 6, j = e & 63;
            se[j][c] = emb[c * KCODES + ch + j];
        }
        if (threadIdx.x < 64) sn[threadIdx.x] = g_enorm[ch + threadIdx.x];
        __syncthreads();

        #pragma unroll 2
        for (int j = 0; j < 64; j++) {
            // row[cc] = floats 4cc..4cc+3 of code row j (correct ulonglong2 step)
            const ulonglong2* row = reinterpret_cast<const ulonglong2*>(&se[j][0]);
            ull d = 0ull;
            #pragma unroll
            for (int cc = 0; cc < 16; cc++) {
                ulonglong2 v = row[cc];
                d = fma2(f2[2 * cc],     v.x, d);
                d = fma2(f2[2 * cc + 1], v.y, d);
            }
            float lo, hi;
            unpack2(d, lo, hi);
            float score = 2.f * (lo + hi) - sn[j];
            if (score > best) { best = score; bestj = ch + j; }
        }
        __syncthreads();
    }

    out_idx[tok] = (float)bestj;

    float lsum = 0.f;
    #pragma unroll
    for (int c2 = 0; c2 < 32; c2++) {
        float x0, x1;
        unpack2(f2[c2], x0, x1);
        float q0 = __ldg(&emb[(2 * c2)     * KCODES + bestj]);
        float q1 = __ldg(&emb[(2 * c2 + 1) * KCODES + bestj]);
        out_q[(size_t)tok * 64 + 2 * c2]     = q0;
        out_q[(size_t)tok * 64 + 2 * c2 + 1] = q1;
        float d0 = q0 - x0, d1 = q1 - x1;
        lsum = fmaf(d0, d0, lsum);
        lsum = fmaf(d1, d1, lsum);
        atomicAdd(&g_dw[(2 * c2)     * KCODES + bestj], x0);
        atomicAdd(&g_dw[(2 * c2 + 1) * KCODES + bestj], x1);
    }
    atomicAdd(&g_counts[bestj], 1);

    #pragma unroll
    for (int o = 16; o > 0; o >>= 1)
        lsum += __shfl_down_sync(0xffffffffu, lsum, o);
    int lane = threadIdx.x & 31, w = threadIdx.x >> 5;
    if (lane == 0) wsum[w] = lsum;
    __syncthreads();
    if (threadIdx.x == 0) {
        float s = 0.f;
        #pragma unroll
        for (int i = 0; i < 8; i++) s += wsum[i];
        atomicAdd(&g_loss, s);
    }
}

// ---- EMA finalize: loss, perplexity, new_embeddings ----
__global__ void finalize_kernel(
    const float* __restrict__ ema_cluster, const float* __restrict__ ema_dw,
    float* __restrict__ out_loss, float* __restrict__ out_perp,
    float* __restrict__ out_emb)
{
    __shared__ float red[1024];
    int j = threadIdx.x;
    const float debias = (float)(1.0 - pow(0.99, 1001.0));

    float cnt = (float)g_counts[j];
    float cs = (ema_cluster[j] * 0.99f + cnt * 0.01f) / debias;

    red[j] = cs;
    __syncthreads();
    for (int s = 512; s > 0; s >>= 1) {
        if (j < s) red[j] += red[j + s];
        __syncthreads();
    }
    float n = red[0];
    __syncthreads();

    float stable = (cs + 1e-5f) / (n + 1024.f * 1e-5f) * n;
    for (int c = 0; c < 64; c++) {
        int idx = c * 1024 + j;
        float upd = (ema_dw[idx] * 0.99f + g_dw[idx] * 0.01f) / debias;
        out_emb[idx] = upd / stable;
    }

    float ap = cnt / (float)NTOK;
    red[j] = ap * logf(ap + 1e-10f);
    __syncthreads();
    for (int s = 512; s > 0; s >>= 1) {
        if (j < s) red[j] += red[j + s];
        __syncthreads();
    }
    if (j == 0) {
        out_perp[0] = expf(-red[0]);
        out_loss[0] = 0.25f * (g_loss / (float)((size_t)NTOK * CDIM));
    }
}

extern "C" void kernel_launch(void* const* d_in, const int* in_sizes, int n_in,
                              void* d_out, int out_size)
{
    const float* states      = (const float*)d_in[0];
    const float* w_se        = (const float*)d_in[1];
    const float* b_se        = (const float*)d_in[2];
    const float* w0          = (const float*)d_in[3];
    const float* b0          = (const float*)d_in[4];
    const float* w1          = (const float*)d_in[5];
    const float* b1          = (const float*)d_in[6];
    const float* w2          = (const float*)d_in[7];
    const float* b2          = (const float*)d_in[8];
    const float* emb         = (const float*)d_in[9];
    const float* ema_cluster = (const float*)d_in[10];
    const float* ema_dw      = (const float*)d_in[11];
    float* out = (float*)d_out;

    float *buf0, *buf1, *lat;
    cudaGetSymbolAddress((void**)&buf0, g_buf0);
    cudaGetSymbolAddress((void**)&buf1, g_buf1);
    cudaGetSymbolAddress((void**)&lat,  g_lat);

    float* out_q    = out;
    float* out_loss = out + 6291456;
    float* out_perp = out + 6291457;
    float* out_idx  = out + 6291458;
    float* out_emb  = out + 6389762;

    init_kernel<<<1, 1024>>>(emb);

    gemm_bias_gelu<128><<<dim3(4, NTOK / 128), 256>>>(states, w_se, b_se, buf0, NTOK, 256, 512);
    gemm_bias_gelu<128><<<dim3(4, NTOK / 128), 256>>>(buf0,   w0,   b0,   buf1, NTOK, 512, 512);
    gemm_bias_gelu<128><<<dim3(4, NTOK / 128), 256>>>(buf1,   w1,   b1,   buf0, NTOK, 512, 512);
    gemm_bias_gelu<64> <<<dim3(1, NTOK / 128), 256>>>(buf0,   w2,   b2,   lat,  NTOK, 512, 64);

    vq_kernel<<<NTOK / 256, 256>>>(lat, emb, out_q, out_idx);

    finalize_kernel<<<1, 1024>>>(ema_cluster, ema_dw, out_loss, out_perp, out_emb);
}

// round 11
// speedup vs baseline: 1.0925x; 1.0026x over previous
#include <cuda_runtime.h>
#include <math.h>

#define NTOK   98304
#define CDIM   64
#define KCODES 1024

typedef unsigned long long ull;

// ---- scratch (no allocations allowed; __device__ globals per harness rules) ----
__device__ float g_buf0[(size_t)NTOK * 512];
__device__ float g_buf1[(size_t)NTOK * 512];
__device__ float g_lat [(size_t)NTOK * CDIM];
__device__ float g_dw  [CDIM * KCODES];
__device__ int   g_counts[KCODES];
__device__ float g_enorm [KCODES];
__device__ float g_loss;

__device__ __forceinline__ float gelu_tanh(float x) {
    float x3 = x * x * x;
    return 0.5f * x * (1.0f + tanhf(0.7978845608028654f * (x + 0.044715f * x3)));
}

// Packed dual-fp32 FMA (Blackwell f32x2 pipe; ptxas never emits this from C++)
__device__ __forceinline__ ull fma2(ull a, ull b, ull c) {
    ull d;
    asm("fma.rn.f32x2 %0, %1, %2, %3;" : "=l"(d) : "l"(a), "l"(b), "l"(c));
    return d;
}
__device__ __forceinline__ ull dup2(float x) {
    ull d;
    asm("mov.b64 %0, {%1, %1};" : "=l"(d) : "f"(x));
    return d;
}
__device__ __forceinline__ ull pack2(float lo, float hi) {
    ull d;
    asm("mov.b64 %0, {%1, %2};" : "=l"(d) : "f"(lo), "f"(hi));
    return d;
}
__device__ __forceinline__ void unpack2(ull d, float& lo, float& hi) {
    asm("mov.b64 {%0, %1}, %2;" : "=f"(lo), "=f"(hi) : "l"(d));
}

// Zero accumulators + precompute code norms: sum_c emb[c][j]^2
__global__ void init_kernel(const float* __restrict__ emb) {
    int t = threadIdx.x;  // 1024 threads
    for (int i = t; i < CDIM * KCODES; i += 1024) g_dw[i] = 0.f;
    g_counts[t] = 0;
    if (t == 0) g_loss = 0.f;
    float s = 0.f;
    #pragma unroll
    for (int c = 0; c < CDIM; c++) {
        float v = emb[c * KCODES + t];
        s = fmaf(v, v, s);
    }
    g_enorm[t] = s;
}

// ---- fp32 GEMM + bias + gelu, f32x2-packed inner product ----
// C[N,M] = gelu(A[N,K] @ W[K,M] + b). TM=128, TN in {128,64}, TK=8.
// 256 threads, micro-tile 8 x NR per thread; acc packed in pairs over N.
// Warp footprint: 8 distinct row-groups x 4 distinct col-groups so A LDS
// broadcasts 4-way (1 wavefront per LDS.128) and B 8-way.
template <int TN>
__global__ __launch_bounds__(256, 2) void gemm_bias_gelu(
    const float* __restrict__ A, const float* __restrict__ W,
    const float* __restrict__ bias, float* __restrict__ C,
    int N, int K, int M)
{
    constexpr int TM = 128, TK = 8;
    constexpr int NR = TN / 16;            // cols per thread (8 or 4)
    constexpr int NP = NR / 2;             // packed col-pairs per thread
    constexpr int BLOAD = (TK * TN) / 4;   // float4s in a B tile
    __shared__ __align__(16) float As[2][TK][TM];
    __shared__ __align__(16) float Bs[2][TK][TN];

    const int tid = threadIdx.x;
    const int lane = tid & 31;
    const int wrp  = tid >> 5;
    const int bm = blockIdx.y * TM;
    const int bn = blockIdx.x * TN;
    // 16x16 thread grid over the 128 x TN tile; warp covers 8 rows x 4 cols.
    const int mt = ((lane & 7) + 8 * (wrp & 1)) * 8;
    const int nt = ((lane >> 3) + 4 * (wrp >> 1)) * NR;

    // A tile: 128 rows x 8 floats = 256 float4, one per thread.
    const int arow = tid >> 1;
    const int acol = (tid & 1) * 4;
    // B tile: 8 x TN floats = BLOAD float4.
    const int brow = (tid < BLOAD) ? tid / (TN / 4) : 0;
    const int bcol = (tid < BLOAD) ? (tid % (TN / 4)) * 4 : 0;

    const float* Aptr = A + (size_t)(bm + arow) * K + acol;
    const float* Wptr = W + (size_t)brow * M + bn + bcol;

    ull acc2[8][NP];
    #pragma unroll
    for (int i = 0; i < 8; i++)
        #pragma unroll
        for (int j = 0; j < NP; j++) acc2[i][j] = 0ull;  // {+0.f, +0.f}

    // Prologue: tile 0 -> buffer 0
    float4 ar = *reinterpret_cast<const float4*>(Aptr);
    float4 br;
    if (tid < BLOAD) br = *reinterpret_cast<const float4*>(Wptr);
    As[0][acol + 0][arow] = ar.x; As[0][acol + 1][arow] = ar.y;
    As[0][acol + 2][arow] = ar.z; As[0][acol + 3][arow] = ar.w;
    if (tid < BLOAD) *reinterpret_cast<float4*>(&Bs[0][brow][bcol]) = br;
    __syncthreads();

    int buf = 0;
    for (int k0 = 0; k0 < K; k0 += TK) {
        const bool more = (k0 + TK) < K;
        if (more) {
            ar = *reinterpret_cast<const float4*>(Aptr + k0 + TK);
            if (tid < BLOAD)
                br = *reinterpret_cast<const float4*>(Wptr + (size_t)(k0 + TK) * M);
        }

        #pragma unroll
        for (int kk = 0; kk < TK; kk++) {
            // A fragment: 8 scalars (2x LDS.128, 4-way lane broadcast)
            float4 a0 = *reinterpret_cast<const float4*>(&As[buf][kk][mt]);
            float4 a1 = *reinterpret_cast<const float4*>(&As[buf][kk][mt + 4]);
            float a[8] = {a0.x, a0.y, a0.z, a0.w, a1.x, a1.y, a1.z, a1.w};
            // B fragment: NP packed pairs. One ulonglong2 = 4 consecutive
            // floats = pairs {2p, 2p+1}, stepping 4 floats per load.
            ull b2[NP];
            #pragma unroll
            for (int p = 0; p < NP / 2; p++) {
                ulonglong2 t = *reinterpret_cast<const ulonglong2*>(&Bs[buf][kk][nt + 4 * p]);
                b2[2 * p] = t.x; b2[2 * p + 1] = t.y;
            }
            #pragma unroll
            for (int i = 0; i < 8; i++) {
                ull ad = dup2(a[i]);
                #pragma unroll
                for (int j = 0; j < NP; j++)
                    acc2[i][j] = fma2(ad, b2[j], acc2[i][j]);
            }
        }

        if (more) {
            int nb = buf ^ 1;
            As[nb][acol + 0][arow] = ar.x; As[nb][acol + 1][arow] = ar.y;
            As[nb][acol + 2][arow] = ar.z; As[nb][acol + 3][arow] = ar.w;
            if (tid < BLOAD) *reinterpret_cast<float4*>(&Bs[nb][brow][bcol]) = br;
        }
        __syncthreads();
        buf ^= 1;
    }

    // Epilogue: unpack pairs, bias + gelu, vectorized store
    float bv[NR];
    #pragma unroll
    for (int j = 0; j < NR; j++) bv[j] = bias[bn + nt + j];
    #pragma unroll
    for (int i = 0; i < 8; i++) {
        float o[NR];
        #pragma unroll
        for (int j = 0; j < NP; j++) {
            float lo, hi;
            unpack2(acc2[i][j], lo, hi);
            o[2 * j]     = gelu_tanh(lo + bv[2 * j]);
            o[2 * j + 1] = gelu_tanh(hi + bv[2 * j + 1]);
        }
        float* crow = C + (size_t)(bm + mt + i) * M + bn + nt;
        #pragma unroll
        for (int j = 0; j < NR / 4; j++)
            *reinterpret_cast<float4*>(crow + 4 * j) =
                make_float4(o[4 * j], o[4 * j + 1], o[4 * j + 2], o[4 * j + 3]);
    }
}

// ---- VQ: per-token argmin over 1024 codes (f32x2 dot), scatter stats ----
__global__ __launch_bounds__(256) void vq_kernel(
    const float* __restrict__ latent, const float* __restrict__ emb,
    float* __restrict__ out_q, float* __restrict__ out_idx)
{
    __shared__ __align__(16) float se[64][68];
    __shared__ float sn[64];
    __shared__ float wsum[8];

    const int tok = blockIdx.x * 256 + threadIdx.x;
    ull f2[32];
    #pragma unroll
    for (int c = 0; c < 64; c += 4) {
        float4 v = *reinterpret_cast<const float4*>(latent + (size_t)tok * 64 + c);
        f2[c / 2]     = pack2(v.x, v.y);
        f2[c / 2 + 1] = pack2(v.z, v.w);
    }

    float best = -3.4e38f;
    int bestj = 0;
    for (int ch = 0; ch < KCODES; ch += 64) {
        #pragma unroll
        for (int r = 0; r < 16; r++) {
            int e = threadIdx.x + r * 256;
            int c = e >> 6, j = e & 63;
            se[j][c] = emb[c * KCODES + ch + j];
        }
        if (threadIdx.x < 64) sn[threadIdx.x] = g_enorm[ch + threadIdx.x];
        __syncthreads();

        #pragma unroll 2
        for (int j = 0; j < 64; j++) {
            const ulonglong2* row = reinterpret_cast<const ulonglong2*>(&se[j][0]);
            ull d = 0ull;
            #pragma unroll
            for (int cc = 0; cc < 16; cc++) {
                ulonglong2 v = row[cc];
                d = fma2(f2[2 * cc],     v.x, d);
                d = fma2(f2[2 * cc + 1], v.y, d);
            }
            float lo, hi;
            unpack2(d, lo, hi);
            float score = 2.f * (lo + hi) - sn[j];
            if (score > best) { best = score; bestj = ch + j; }
        }
        __syncthreads();
    }

    out_idx[tok] = (float)bestj;

    float lsum = 0.f;
    #pragma unroll
    for (int c2 = 0; c2 < 32; c2++) {
        float x0, x1;
        unpack2(f2[c2], x0, x1);
        float q0 = __ldg(&emb[(2 * c2)     * KCODES + bestj]);
        float q1 = __ldg(&emb[(2 * c2 + 1) * KCODES + bestj]);
        out_q[(size_t)tok * 64 + 2 * c2]     = q0;
        out_q[(size_t)tok * 64 + 2 * c2 + 1] = q1;
        float d0 = q0 - x0, d1 = q1 - x1;
        lsum = fmaf(d0, d0, lsum);
        lsum = fmaf(d1, d1, lsum);
        atomicAdd(&g_dw[(2 * c2)     * KCODES + bestj], x0);
        atomicAdd(&g_dw[(2 * c2 + 1) * KCODES + bestj], x1);
    }
    atomicAdd(&g_counts[bestj], 1);

    #pragma unroll
    for (int o = 16; o > 0; o >>= 1)
        lsum += __shfl_down_sync(0xffffffffu, lsum, o);
    int lane = threadIdx.x & 31, w = threadIdx.x >> 5;
    if (lane == 0) wsum[w] = lsum;
    __syncthreads();
    if (threadIdx.x == 0) {
        float s = 0.f;
        #pragma unroll
        for (int i = 0; i < 8; i++) s += wsum[i];
        atomicAdd(&g_loss, s);
    }
}

// ---- EMA finalize: loss, perplexity, new_embeddings ----
__global__ void finalize_kernel(
    const float* __restrict__ ema_cluster, const float* __restrict__ ema_dw,
    float* __restrict__ out_loss, float* __restrict__ out_perp,
    float* __restrict__ out_emb)
{
    __shared__ float red[1024];
    int j = threadIdx.x;
    const float debias = (float)(1.0 - pow(0.99, 1001.0));

    float cnt = (float)g_counts[j];
    float cs = (ema_cluster[j] * 0.99f + cnt * 0.01f) / debias;

    red[j] = cs;
    __syncthreads();
    for (int s = 512; s > 0; s >>= 1) {
        if (j < s) red[j] += red[j + s];
        __syncthreads();
    }
    float n = red[0];
    __syncthreads();

    float stable = (cs + 1e-5f) / (n + 1024.f * 1e-5f) * n;
    for (int c = 0; c < 64; c++) {
        int idx = c * 1024 + j;
        float upd = (ema_dw[idx] * 0.99f + g_dw[idx] * 0.01f) / debias;
        out_emb[idx] = upd / stable;
    }

    float ap = cnt / (float)NTOK;
    red[j] = ap * logf(ap + 1e-10f);
    __syncthreads();
    for (int s = 512; s > 0; s >>= 1) {
        if (j < s) red[j] += red[j + s];
        __syncthreads();
    }
    if (j == 0) {
        out_perp[0] = expf(-red[0]);
        out_loss[0] = 0.25f * (g_loss / (float)((size_t)NTOK * CDIM));
    }
}

extern "C" void kernel_launch(void* const* d_in, const int* in_sizes, int n_in,
                              void* d_out, int out_size)
{
    const float* states      = (const float*)d_in[0];
    const float* w_se        = (const float*)d_in[1];
    const float* b_se        = (const float*)d_in[2];
    const float* w0          = (const float*)d_in[3];
    const float* b0          = (const float*)d_in[4];
    const float* w1          = (const float*)d_in[5];
    const float* b1          = (const float*)d_in[6];
    const float* w2          = (const float*)d_in[7];
    const float* b2          = (const float*)d_in[8];
    const float* emb         = (const float*)d_in[9];
    const float* ema_cluster = (const float*)d_in[10];
    const float* ema_dw      = (const float*)d_in[11];
    float* out = (float*)d_out;

    float *buf0, *buf1, *lat;
    cudaGetSymbolAddress((void**)&buf0, g_buf0);
    cudaGetSymbolAddress((void**)&buf1, g_buf1);
    cudaGetSymbolAddress((void**)&lat,  g_lat);

    float* out_q    = out;
    float* out_loss = out + 6291456;
    float* out_perp = out + 6291457;
    float* out_idx  = out + 6291458;
    float* out_emb  = out + 6389762;

    init_kernel<<<1, 1024>>>(emb);

    gemm_bias_gelu<128><<<dim3(4, NTOK / 128), 256>>>(states, w_se, b_se, buf0, NTOK, 256, 512);
    gemm_bias_gelu<128><<<dim3(4, NTOK / 128), 256>>>(buf0,   w0,   b0,   buf1, NTOK, 512, 512);
    gemm_bias_gelu<128><<<dim3(4, NTOK / 128), 256>>>(buf1,   w1,   b1,   buf0, NTOK, 512, 512);
    gemm_bias_gelu<64> <<<dim3(1, NTOK / 128), 256>>>(buf0,   w2,   b2,   lat,  NTOK, 512, 64);

    vq_kernel<<<NTOK / 256, 256>>>(lat, emb, out_q, out_idx);

    finalize_kernel<<<1, 1024>>>(ema_cluster, ema_dw, out_loss, out_perp, out_emb);
}